// round 1
// baseline (speedup 1.0000x reference)
#include <cuda_runtime.h>
#include <math.h>

// Per-batch 2x2 affine matrix (translation terms are analytically zero):
// A00 A01 A10 A11 per batch.
__device__ float g_A[256 * 4];

__global__ void mats_kernel(const float* __restrict__ thetas,
                            const float* __restrict__ l1s,
                            const float* __restrict__ l2s, int B) {
    int b = blockIdx.x * blockDim.x + threadIdx.x;
    if (b >= B) return;
    double th = (double)thetas[b];
    double c = cos(th), s = sin(th);
    double i1 = 1.0 / (double)l1s[b];
    double i2 = 1.0 / (double)l2s[b];
    g_A[b * 4 + 0] = (float)(c * c * i1 + s * s * i2);
    g_A[b * 4 + 1] = (float)(c * s * (i1 - i2));
    g_A[b * 4 + 2] = (float)(c * s * (i1 - i2));
    g_A[b * 4 + 3] = (float)(s * s * i1 + c * c * i2);
}

__global__ __launch_bounds__(256)
void warp_kernel(const float* __restrict__ x, float* __restrict__ out,
                 int B, int C, int H, int W) {
    int w = blockIdx.x * blockDim.x + threadIdx.x;
    int h = blockIdx.y;
    int b = blockIdx.z;
    if (w >= W) return;

    const float4 A = *reinterpret_cast<const float4*>(g_A + b * 4);

    float xn = ((float)w + 0.5f) * (2.0f / (float)W) - 1.0f;
    float yn = ((float)h + 0.5f) * (2.0f / (float)H) - 1.0f;

    // normalized grid coords (translation is zero), then to pixel coords
    float gx = (A.x * xn + A.y * yn + 1.0f) * ((float)W * 0.5f) - 0.5f;
    float gy = (A.z * xn + A.w * yn + 1.0f) * ((float)H * 0.5f) - 0.5f;

    int HW = H * W;
    float* op = out + (b * C) * HW + h * W + w;

    // Fully out of bounds -> all four taps have zero weight.
    if (!(gx > -1.0f) || gx >= (float)W || !(gy > -1.0f) || gy >= (float)H) {
        #pragma unroll
        for (int c = 0; c < 3; c++) op[c * HW] = 0.0f;
        return;
    }

    float x0f = floorf(gx), y0f = floorf(gy);
    int x0 = (int)x0f, y0 = (int)y0f;
    int x1 = x0 + 1, y1 = y0 + 1;
    float wx1 = gx - x0f, wx0 = 1.0f - wx1;
    float wy1 = gy - y0f, wy0 = 1.0f - wy1;

    // zero-padding masks are separable per coordinate
    float fx0 = (x0 >= 0 && x0 < W) ? wx0 : 0.0f;
    float fx1 = (x1 >= 0 && x1 < W) ? wx1 : 0.0f;
    float fy0 = (y0 >= 0 && y0 < H) ? wy0 : 0.0f;
    float fy1 = (y1 >= 0 && y1 < H) ? wy1 : 0.0f;

    int xc0 = min(max(x0, 0), W - 1);
    int xc1 = min(max(x1, 0), W - 1);
    int yc0 = min(max(y0, 0), H - 1);
    int yc1 = min(max(y1, 0), H - 1);

    int o00 = yc0 * W + xc0;
    int o01 = yc0 * W + xc1;
    int o10 = yc1 * W + xc0;
    int o11 = yc1 * W + xc1;

    const float* base = x + (b * C) * HW;
    #pragma unroll
    for (int c = 0; c < 3; c++) {
        const float* p = base + c * HW;
        float v = fy0 * (fx0 * __ldg(p + o00) + fx1 * __ldg(p + o01)) +
                  fy1 * (fx0 * __ldg(p + o10) + fx1 * __ldg(p + o11));
        op[c * HW] = v;
    }
}

extern "C" void kernel_launch(void* const* d_in, const int* in_sizes, int n_in,
                              void* d_out, int out_size) {
    const float* x      = (const float*)d_in[0];
    const float* thetas = (const float*)d_in[1];
    const float* l1s    = (const float*)d_in[2];
    const float* l2s    = (const float*)d_in[3];
    float* out = (float*)d_out;

    int B = in_sizes[1];
    int C = 3;
    long long hw = (long long)in_sizes[0] / ((long long)B * C);
    int W = (int)(sqrt((double)hw) + 0.5);
    int H = (int)(hw / W);

    mats_kernel<<<1, 256>>>(thetas, l1s, l2s, B);

    dim3 block(256, 1, 1);
    dim3 grid((W + 255) / 256, H, B);
    warp_kernel<<<grid, block>>>(x, out, B, C, H, W);
}